// round 16
// baseline (speedup 1.0000x reference)
#include <cuda_runtime.h>
#include <cstdint>
#include <cstddef>

#define NEGF (-1e20f)

constexpr int NA   = 512;
constexpr int NBC  = 1024;
constexpr int WIN  = 8;
constexpr int NWIN = 68;           // steps 1..544 (543 needed)
constexpr int NT   = 128;          // warp0 = compute, warps 1-3 = helpers

constexpr int BAND_F = 2 * WIN * 32 * 32;            // 16384 floats per band
constexpr size_t SMEM_B = (size_t)3 * BAND_F * 4 + 2 * 32 * 4;

__device__ __forceinline__ float p2(int d) {
    int k = d + 127;
    k = max(k, 0); k = min(k, 254);
    return __int_as_float(k << 23);
}
__device__ __forceinline__ int swz(int t, int m) {
    return ((((m >> 2) ^ (t & 7)) << 2) | (m & 3));
}
__device__ __forceinline__ void cpa16(uint32_t dst, const void* src) {
    asm volatile("cp.async.cg.shared.global [%0], [%1], 16;" :: "r"(dst), "l"(src));
}

__global__ void __launch_bounds__(NT, 1)
dtw_ws_kernel(const float* __restrict__ W, float* __restrict__ out) {
    extern __shared__ float sm[];
    float* F   = sm;                       // [2][WIN][32][32] exp(W), swizzled
    float* RAW = sm + BAND_F;              // [2][WIN][32][32] raw W, linear
    float* O   = sm + 2 * BAND_F;          // [2][WIN][32][32] outputs, swizzled
    int*   EB  = (int*)(sm + 3 * BAND_F);  // [2][32] per-thread window e_base

    const int tid = threadIdx.x, lane = tid & 31, wid = tid >> 5;
    const int b = blockIdx.x;
    const float* Wb = W + (size_t)b * NA * NBC;
    float* Ob = out + (size_t)b * (NA + 1) * (NBC + 1);
    const uint32_t RAWs = (uint32_t)__cvta_generic_to_shared(RAW);

    // ---- edge outputs ----
    for (int k = tid; k <= NBC; k += NT) Ob[k] = k ? NEGF : 0.0f;
    for (int r = 1 + tid; r <= NA; r += NT) Ob[(size_t)r * (NBC + 1)] = NEGF;

    // ---- compute-warp state ----
    float tm[32];
    #pragma unroll
    for (int k = 0; k < 32; ++k) tm[k] = 0.0f;
    int   ebo = 0;
    float pl  = (lane == 0) ? 0.0f : 1.0f;
    float pm  = 0.0f;
    float pm_s = (lane == 0) ? 1.0f : 0.0f;   // seed mu[0][0]=0 -> 1.0@2^0

    // ---- helper lambdas ----
    const int h = wid - 1;
    const int pstart = (h == 0) ? 0 : (h == 1) ? 86 : 172;
    const int pend   = (h == 0) ? 86 : (h == 1) ? 172 : 256;

    auto fill = [&](int wt) {   // cp.async raw W slab for window wt
        const int par = wt & 1;
        for (int g0 = pstart; g0 < pend; g0 += 4) {
            int p = g0 + (lane >> 3);
            int fl = lane & 7;
            if (p < pend) {
                int q = p >> 5, t = p & 31;
                int r = 8 * wt + q - t;
                if (0 <= r && r < NA) {
                    uint32_t dst = RAWs +
                        (uint32_t)((((par * WIN + q) * 32 + t) * 32 + fl * 4) * 4);
                    cpa16(dst, Wb + (size_t)r * NBC + t * 32 + fl * 4);
                }
            }
        }
    };
    auto xform = [&](int wt) {  // raw -> exp(W) band (0 for invalid rows)
        const int par = wt & 1;
        for (int p = pstart; p < pend; ++p) {
            int q = p >> 5, t = p & 31;
            int r = 8 * wt + q - t;
            int base = ((par * WIN + q) * 32 + t) * 32;
            float v = RAW[base + lane];
            F[base + swz(t, lane)] = (0 <= r && r < NA) ? __expf(v) : 0.0f;
        }
    };
    auto flushw = [&](int wf) { // O band -> log-domain global outputs
        const int par = wf & 1;
        for (int p = pstart; p < pend; ++p) {
            int q = p >> 5, t = p & 31;
            int i = 8 * wf + q + 1 - t;
            if (1 <= i && i <= NA) {
                float v = O[((par * WIN + q) * 32 + t) * 32 + swz(t, lane)];
                float eb = (float)EB[par * 32 + t];
                Ob[(size_t)i * (NBC + 1) + t * 32 + lane + 1] =
                    (__log2f(fmaxf(v, 1e-37f)) + eb) * 0.6931471805599453f;
            }
        }
    };

    // ---- prologue ----
    if (wid) {
        fill(0); asm volatile("cp.async.commit_group;" ::: "memory");
        fill(1); asm volatile("cp.async.commit_group;" ::: "memory");
        asm volatile("cp.async.wait_group 1;" ::: "memory");
        __syncwarp();
        xform(0);
    } else {
        EB[lane] = 0;   // window 0, parity 0
    }
    __syncthreads();

    // ---- main loop ----
    for (int w = 0; w < NWIN; ++w) {
        if (wid == 0) {
            if (w) {   // window-boundary rescale (off the step path)
                float vmax = tm[0];
                #pragma unroll
                for (int k = 1; k < 32; ++k) vmax = fmaxf(vmax, tm[k]);
                int sh = (vmax > 0.0f) ? ((__float_as_int(vmax) >> 23) - 127) : 0;
                int e = ebo + sh;
                #pragma unroll
                for (int d = 1; d < 32; d <<= 1) {
                    int o = __shfl_up_sync(0xFFFFFFFFu, e, d);
                    if (lane >= d) e = max(e, o);
                }
                float rho   = p2(ebo - e);
                int eb_nb   = __shfl_up_sync(0xFFFFFFFFu, e, 1);
                float rho_n = __shfl_up_sync(0xFFFFFFFFu, rho, 1);
                pl = (lane == 0) ? 0.0f : p2(eb_nb - e);
                #pragma unroll
                for (int k = 0; k < 32; ++k) tm[k] *= rho;
                pm   = (lane == 0) ? 0.0f : pm * rho_n;
                pm_s = pm * pl;
                ebo  = e;
                EB[(w & 1) * 32 + lane] = e;
            }
            const float4* fB = (const float4*)F + (size_t)(w & 1) * WIN * 32 * 8 + lane * 8;
            float4*       oB = (float4*)O       + (size_t)(w & 1) * WIN * 32 * 8 + lane * 8;
            const int sx = lane & 7;

            #pragma unroll 1
            for (int q = 0; q < WIN; ++q) {
                const float4* fq = fB + q * 256;
                float4 f4[8];
                #pragma unroll
                for (int mb = 0; mb < 8; ++mb) f4[mb] = fq[mb ^ sx];
                float fv[32];
                #pragma unroll
                for (int mb = 0; mb < 8; ++mb) {
                    fv[4*mb]   = f4[mb].x; fv[4*mb+1] = f4[mb].y;
                    fv[4*mb+2] = f4[mb].z; fv[4*mb+3] = f4[mb].w;
                }

                float lvraw = __shfl_up_sync(0xFFFFFFFFu, tm[31], 1);
                if (lane == 0) lvraw = 0.0f;

                float b0 = (tm[0] + pm_s) * fv[0];
                float c  = fmaf(lvraw, pl * fv[0], b0);
                float tprev = tm[0]; tm[0] = c;
                #pragma unroll
                for (int k = 1; k < 32; ++k) {
                    float told = tm[k];
                    float g = (told + tprev) * fv[k];
                    c = fmaf(c, fv[k], g);
                    tm[k] = c; tprev = told;
                }
                pm = lvraw; pm_s = lvraw * pl;

                float4* oq = oB + q * 256;
                #pragma unroll
                for (int mb = 0; mb < 8; ++mb)
                    oq[mb ^ sx] = make_float4(tm[4*mb], tm[4*mb+1],
                                              tm[4*mb+2], tm[4*mb+3]);
            }
        } else {
            if (w + 2 < NWIN) fill(w + 2);
            asm volatile("cp.async.commit_group;" ::: "memory");
            asm volatile("cp.async.wait_group 1;" ::: "memory");
            __syncwarp();
            if (w + 1 < NWIN) xform(w + 1);
            if (w >= 1) flushw(w - 1);
        }
        __syncthreads();
    }

    if (wid) flushw(NWIN - 1);
}

extern "C" void kernel_launch(void* const* d_in, const int* in_sizes, int n_in,
                              void* d_out, int out_size) {
    const float* W = (const float*)d_in[0];
    float* out = (float*)d_out;
    cudaFuncSetAttribute(dtw_ws_kernel,
                         cudaFuncAttributeMaxDynamicSharedMemorySize,
                         (int)SMEM_B);
    dtw_ws_kernel<<<32, NT, SMEM_B>>>(W, out);
}